// round 9
// baseline (speedup 1.0000x reference)
#include <cuda_runtime.h>
#include <cuda_bf16.h>

// Persistent kernel. Gathers use warp-coalesced LDG.32 so every load
// instruction touches exactly ONE 128B line (cross-LDG wavefronts at
// ~1.0 cyc/wf instead of 4 within-LDG replay wavefronts at 2.07 cyc for a
// 512B-spanning LDG.128).
// Warp chunk = 8 edges, processed as 4 pairs. Per pair: 16 independent
// coalesced LDG.32 (4 rows x 4 line-chunks; lane l reads element 32c+l),
// 8 FMAs/lane, two 5-level butterfly reductions, lane 0 stores a float2.
// Next chunk's indices prefetched before the pair loop.
__global__ void __launch_bounds__(256, 5) edge_dot_kernel(
    const float* __restrict__ h,
    const int* __restrict__ src,
    const int* __restrict__ dst,
    float* __restrict__ out,
    int n_edges)
{
    const int wib  = threadIdx.x >> 5;
    const int lane = threadIdx.x & 31;
    const unsigned FULL = 0xFFFFFFFFu;

    const int W = blockIdx.x * 8 + wib;       // global warp id
    const int stride = gridDim.x * 64;        // edges per sweep

    int e0 = W * 8;
    if (e0 >= n_edges) return;

    // indices for first chunk: lanes 0-7 src[e0+lane], lanes 8-15 dst[e0+lane-8]
    int idx = 0;
    if (lane < 16) {
        int ei = e0 + (lane & 7);
        if (ei < n_edges)
            idx = (lane < 8) ? __ldg(src + ei) : __ldg(dst + ei);
    }

    while (true) {
        // ---- prefetch next chunk's indices
        int e0n = e0 + stride;
        int idx_next = 0;
        if (e0n < n_edges && lane < 16) {
            int ei = e0n + (lane & 7);
            if (ei < n_edges)
                idx_next = (lane < 8) ? __ldg(src + ei) : __ldg(dst + ei);
        }

        #pragma unroll
        for (int p = 0; p < 4; p++) {
            int sA = __shfl_sync(FULL, idx, 2 * p);
            int sB = __shfl_sync(FULL, idx, 2 * p + 1);
            int dA = __shfl_sync(FULL, idx, 8 + 2 * p);
            int dB = __shfl_sync(FULL, idx, 8 + 2 * p + 1);

            const float* psA = h + (size_t)sA * 128 + lane;
            const float* pdA = h + (size_t)dA * 128 + lane;
            const float* psB = h + (size_t)sB * 128 + lane;
            const float* pdB = h + (size_t)dB * 128 + lane;

            // 16 independent single-line coalesced loads
            float a0 = __ldg(psA);      float a1 = __ldg(psA + 32);
            float a2 = __ldg(psA + 64); float a3 = __ldg(psA + 96);
            float b0 = __ldg(pdA);      float b1 = __ldg(pdA + 32);
            float b2 = __ldg(pdA + 64); float b3 = __ldg(pdA + 96);
            float c0 = __ldg(psB);      float c1 = __ldg(psB + 32);
            float c2 = __ldg(psB + 64); float c3 = __ldg(psB + 96);
            float f0 = __ldg(pdB);      float f1 = __ldg(pdB + 32);
            float f2 = __ldg(pdB + 64); float f3 = __ldg(pdB + 96);

            float accA = a0 * b0;
            accA = fmaf(a1, b1, accA);
            accA = fmaf(a2, b2, accA);
            accA = fmaf(a3, b3, accA);

            float accB = c0 * f0;
            accB = fmaf(c1, f1, accB);
            accB = fmaf(c2, f2, accB);
            accB = fmaf(c3, f3, accB);

            // full-warp butterflies (both edges together)
            #pragma unroll
            for (int m = 16; m > 0; m >>= 1) {
                accA += __shfl_xor_sync(FULL, accA, m);
                accB += __shfl_xor_sync(FULL, accB, m);
            }

            if (lane == 0) {
                int ea = e0 + 2 * p;
                if (ea + 1 < n_edges) {
                    *reinterpret_cast<float2*>(out + ea) = make_float2(accA, accB);
                } else if (ea < n_edges) {
                    out[ea] = accA;
                }
            }
        }

        if (e0n >= n_edges) break;
        e0 = e0n;
        idx = idx_next;
    }
}

extern "C" void kernel_launch(void* const* d_in, const int* in_sizes, int n_in,
                              void* d_out, int out_size)
{
    const float* h   = (const float*)d_in[0];
    const int*   src = (const int*)d_in[1];
    const int*   dst = (const int*)d_in[2];
    float* out = (float*)d_out;

    int n_edges = in_sizes[1];               // E = 640000

    int grid = 6 * 148;                      // persistent sweep
    int max_grid = (n_edges + 63) / 64;      // every warp gets >=1 chunk
    if (grid > max_grid) grid = max_grid;

    edge_dot_kernel<<<grid, 256>>>(h, src, dst, out, n_edges);
}